// round 14
// baseline (speedup 1.0000x reference)
#include <cuda_runtime.h>

// Math collapse: K and V rows are identical across the sequence dim (age is
// broadcast before the K/V projections), so every score row is constant,
// softmax weights are exactly 1/N, and attended[b,n,:] == age[b]@Wv + bv.
// Output = pixel + broadcast(age @ Wv + bv) over n.
//
// R14: proven R6 stream-loop shape (flat mod-24 index, LDS vb, unroll 8 ->
// ptxas batches ~8 LDG.128, HBM 3716 GB/s) combined with:
//  - balanced single wave: grid 512 x 256thr, 4 CTA/SM (68 SMs x 32 warps,
//    80 x 24; R6 left 40 SMs at 16 warps),
//  - zero-register preamble overlap: prefetch.global.L2 of the whole read
//    tile before the vb GEMV, so DRAM serves stream reads during it
//    (R13's register-array prologue spilled; prefetch holds no data).

#define B_DIM 8
#define N_DIM 2048
#define D_DIM 768
#define A_DIM 128

#define DCH   8                        // d-chunks of 96 floats
#define NCH   8                        // n-chunks of 256 rows
#define DSUB  96
#define DSUB4 24                       // float4 per d-chunk
#define NROWS 256
#define TPB   256
#define KSPL  2
#define RSTRIDE4 (D_DIM / 4)           // 192 float4 per full row
#define TOTAL4 (NROWS * DSUB4)         // 6144 float4 per block tile
#define LINES  (NROWS * 3)             // 768 x 128B lines per tile (96f = 3 lines)

__global__ __launch_bounds__(TPB, 4)
void fused_cross_attn_kernel(const float* __restrict__ pixel,
                             const float* __restrict__ age,
                             const float* __restrict__ Wv,
                             const float* __restrict__ bv,
                             float* __restrict__ out) {
    __shared__ __align__(16) float s_age[A_DIM];
    __shared__ __align__(16) float s_part[KSPL * DSUB];
    __shared__ __align__(16) float s_vb[DSUB];

    const int tid = threadIdx.x;
    const int dch = blockIdx.x;        // 0..7
    const int nch = blockIdx.y;        // 0..7
    const int b   = blockIdx.z;        // 0..7
    const int d0  = dch * DSUB;

    if (tid < A_DIM) s_age[tid] = age[b * A_DIM + tid];

    const int n0    = nch * NROWS;
    const int tile4 = (b * N_DIM + n0) * RSTRIDE4 + dch * DSUB4;
    const float4* __restrict__ p4 = reinterpret_cast<const float4*>(pixel) + tile4;
    float4* __restrict__       o4 = reinterpret_cast<float4*>(out) + tile4;

    // ---- L2 prefetch of the whole read tile (fire-and-forget, 3/thread)
#pragma unroll
    for (int j = 0; j < LINES / TPB; j++) {
        const int line = tid + j * TPB;            // 0..767
        const int row  = line / 3;                 // const-div
        const int cl   = line - row * 3;
        const float4* a = p4 + row * RSTRIDE4 + cl * 8;   // 8 float4 = 128B
        asm volatile("prefetch.global.L2 [%0];" :: "l"(a));
    }
    __syncthreads();                               // s_age ready

    // ---- preamble: vb slice via split-K x2 (192 threads, 64-long dots)
    if (tid < KSPL * DSUB) {
        const int dl = tid % DSUB;
        const int k  = tid / DSUB;                 // 0..1
        const int dg = d0 + dl;
        float acc = 0.f;
#pragma unroll
        for (int i = 0; i < A_DIM / KSPL; i++) {
            const int a = k * (A_DIM / KSPL) + i;
            acc = fmaf(s_age[a], Wv[a * D_DIM + dg], acc);
        }
        s_part[k * DSUB + dl] = acc;
    }
    __syncthreads();
    if (tid < DSUB) {
        s_vb[tid] = bv[d0 + tid] + (s_part[tid] + s_part[DSUB + tid]);
    }
    __syncthreads();

    // ---- stream: out tile = pixel tile + vb (R6-proven loop shape)
    const float4* __restrict__ v4 = reinterpret_cast<const float4*>(s_vb);
#pragma unroll 8
    for (int i4 = tid; i4 < TOTAL4; i4 += TPB) {
        const int row = i4 / DSUB4;                // const-div
        const int c   = i4 - row * DSUB4;          // 0..23
        const int a   = row * RSTRIDE4 + c;
        float4 p = p4[a];
        float4 v = v4[c];                          // conflict-free LDS.128
        p.x += v.x; p.y += v.y; p.z += v.z; p.w += v.w;
        o4[a] = p;
    }
}

extern "C" void kernel_launch(void* const* d_in, const int* in_sizes, int n_in,
                              void* d_out, int out_size) {
    // metadata order: pixel_features, age_features, Wq, bq, Wk, bk, Wv, bv
    const float* pixel = (const float*)d_in[0];
    const float* age   = (const float*)d_in[1];
    const float* Wv    = (const float*)d_in[6];
    const float* bv    = (const float*)d_in[7];
    float* out = (float*)d_out;

    dim3 grid(DCH, NCH, B_DIM);
    fused_cross_attn_kernel<<<grid, TPB>>>(pixel, age, Wv, bv, out);
}

// round 15
// speedup vs baseline: 1.4359x; 1.4359x over previous
#include <cuda_runtime.h>

// Math collapse: K and V rows are identical across the sequence dim (age is
// broadcast before the K/V projections), so every score row is constant,
// softmax weights are exactly 1/N, and attended[b,n,:] == age[b]@Wv + bv.
// Output = pixel + broadcast(age @ Wv + bv) over n.
//
// R15: single-variable experiment. The proven R6 stream loop (flat mod-24
// index, LDS vb, unroll 8 -> HBM 3716 GB/s) moved to a balanced single wave:
// grid 512 x 256thr at 4 CTA/SM (68 SMs x 4 CTAs, 80 x 3; R6's 256x512 left
// 40 SMs at half occupancy). No prefetch (R14: -34% BW), no register-array
// prologue (R13: spills).

#define B_DIM 8
#define N_DIM 2048
#define D_DIM 768
#define A_DIM 128

#define DCH   8                        // d-chunks of 96 floats
#define NCH   8                        // n-chunks of 256 rows
#define DSUB  96
#define DSUB4 24                       // float4 per d-chunk
#define NROWS 256
#define TPB   256
#define KSPL  2
#define RSTRIDE4 (D_DIM / 4)           // 192 float4 per full row
#define TOTAL4 (NROWS * DSUB4)         // 6144 float4 per block tile

__global__ __launch_bounds__(TPB, 4)
void fused_cross_attn_kernel(const float* __restrict__ pixel,
                             const float* __restrict__ age,
                             const float* __restrict__ Wv,
                             const float* __restrict__ bv,
                             float* __restrict__ out) {
    __shared__ __align__(16) float s_age[A_DIM];
    __shared__ __align__(16) float s_part[KSPL * DSUB];
    __shared__ __align__(16) float s_vb[DSUB];

    const int tid = threadIdx.x;
    const int dch = blockIdx.x;        // 0..7
    const int nch = blockIdx.y;        // 0..7
    const int b   = blockIdx.z;        // 0..7
    const int d0  = dch * DSUB;

    if (tid < A_DIM) s_age[tid] = age[b * A_DIM + tid];
    __syncthreads();

    // ---- preamble: vb slice via split-K x2 (192 threads, 64-long dots)
    if (tid < KSPL * DSUB) {
        const int dl = tid % DSUB;
        const int k  = tid / DSUB;                 // 0..1
        const int dg = d0 + dl;
        float acc = 0.f;
#pragma unroll
        for (int i = 0; i < A_DIM / KSPL; i++) {
            const int a = k * (A_DIM / KSPL) + i;
            acc = fmaf(s_age[a], Wv[a * D_DIM + dg], acc);
        }
        s_part[k * DSUB + dl] = acc;
    }
    __syncthreads();
    if (tid < DSUB) {
        s_vb[tid] = bv[d0 + tid] + (s_part[tid] + s_part[DSUB + tid]);
    }
    __syncthreads();

    // ---- stream: out[b, n0:n0+256, d0:d0+96] = pixel + vb (R6 loop shape)
    const int n0    = nch * NROWS;
    const int tile4 = (b * N_DIM + n0) * RSTRIDE4 + dch * DSUB4;
    const float4* __restrict__ p4 = reinterpret_cast<const float4*>(pixel) + tile4;
    float4* __restrict__       o4 = reinterpret_cast<float4*>(out) + tile4;
    const float4* __restrict__ v4 = reinterpret_cast<const float4*>(s_vb);

#pragma unroll 8
    for (int i4 = tid; i4 < TOTAL4; i4 += TPB) {
        const int row = i4 / DSUB4;                // const-div -> mul/shift
        const int c   = i4 - row * DSUB4;          // 0..23
        const int a   = row * RSTRIDE4 + c;
        float4 p = p4[a];
        float4 v = v4[c];                          // conflict-free LDS.128
        p.x += v.x; p.y += v.y; p.z += v.z; p.w += v.w;
        o4[a] = p;
    }
}

extern "C" void kernel_launch(void* const* d_in, const int* in_sizes, int n_in,
                              void* d_out, int out_size) {
    // metadata order: pixel_features, age_features, Wq, bq, Wk, bk, Wv, bv
    const float* pixel = (const float*)d_in[0];
    const float* age   = (const float*)d_in[1];
    const float* Wv    = (const float*)d_in[6];
    const float* bv    = (const float*)d_in[7];
    float* out = (float*)d_out;

    dim3 grid(DCH, NCH, B_DIM);
    fused_cross_attn_kernel<<<grid, TPB>>>(pixel, age, Wv, bv, out);
}